// round 1
// baseline (speedup 1.0000x reference)
#include <cuda_runtime.h>
#include <math.h>

#define BB 128
#define LL 128
#define NH 2048
#define DT 0.042f
#define THETA 0.1f
#define ALPHA 0.3f
#define BETA 0.4f

// Persistent state in device globals (no allocation allowed).
__device__ float g_hyA[BB * NH];
__device__ float g_hyB[BB * NH];
__device__ float g_hz[BB * NH];
__device__ float g_ref[BB * NH];
__device__ float g_ssum[BB * NH];

#define TM 32
#define TN 64
#define BK 32

__global__ void init_kernel() {
    int i = blockIdx.x * blockDim.x + threadIdx.x;
    if (i < BB * NH) {
        g_hyA[i] = 0.f;
        g_hz[i] = 0.f;
        g_ref[i] = 0.f;
        g_ssum[i] = 0.f;
    }
}

// One timestep: out[b][n] = update( sum_k hy_in[b][k] * h2h[k][n] + x[b][t]*x2h[n] + bias[n] )
__global__ __launch_bounds__(256) void step_kernel(
    const float* __restrict__ hy_in,
    float* __restrict__ hy_out,
    const float* __restrict__ x,
    const float* __restrict__ h2h,
    const float* __restrict__ x2h,
    const float* __restrict__ bias,
    const float* __restrict__ gamma,
    const float* __restrict__ eps,
    int t)
{
    __shared__ float As[BK][TM + 1];  // k-major: As[k][b]  (padded to kill conflicts)
    __shared__ float Bs[BK][TN];      // Bs[k][n]

    const int tid = threadIdx.x;
    const int tx = tid & 15;   // 0..15 -> cols tx*4 .. tx*4+3
    const int ty = tid >> 4;   // 0..15 -> rows ty, ty+16
    const int n0 = blockIdx.x * TN;
    const int b0 = blockIdx.y * TM;

    // Global-load mapping
    const int a_r = tid >> 3;          // 0..31  (batch row in tile)
    const int a_c = (tid & 7) * 4;     // k offset (float4)
    const int bl_r = tid >> 4;         // 0..15  (k row in tile; also +16)
    const int bl_c = (tid & 15) * 4;   // n offset (float4)

    float acc[2][4] = {{0.f, 0.f, 0.f, 0.f}, {0.f, 0.f, 0.f, 0.f}};

    for (int k0 = 0; k0 < NH; k0 += BK) {
        // A tile: hy_in[b0+a_r][k0+a_c .. +3] -> transposed into As[k][b]
        float4 av = *reinterpret_cast<const float4*>(&hy_in[(b0 + a_r) * NH + k0 + a_c]);
        As[a_c + 0][a_r] = av.x;
        As[a_c + 1][a_r] = av.y;
        As[a_c + 2][a_r] = av.z;
        As[a_c + 3][a_r] = av.w;

        // B tile: h2h[k0 + {bl_r, bl_r+16}][n0 + bl_c ..]
        float4 bv0 = *reinterpret_cast<const float4*>(&h2h[(k0 + bl_r) * NH + n0 + bl_c]);
        float4 bv1 = *reinterpret_cast<const float4*>(&h2h[(k0 + bl_r + 16) * NH + n0 + bl_c]);
        *reinterpret_cast<float4*>(&Bs[bl_r][bl_c]) = bv0;
        *reinterpret_cast<float4*>(&Bs[bl_r + 16][bl_c]) = bv1;

        __syncthreads();

#pragma unroll
        for (int kk = 0; kk < BK; kk++) {
            float a0 = As[kk][ty];
            float a1 = As[kk][ty + 16];
            float4 bq = *reinterpret_cast<const float4*>(&Bs[kk][tx * 4]);
            acc[0][0] += a0 * bq.x; acc[0][1] += a0 * bq.y;
            acc[0][2] += a0 * bq.z; acc[0][3] += a0 * bq.w;
            acc[1][0] += a1 * bq.x; acc[1][1] += a1 * bq.y;
            acc[1][2] += a1 * bq.z; acc[1][3] += a1 * bq.w;
        }
        __syncthreads();
    }

    // Epilogue: bio_cell state update + spike accumulation
    const float ref_decay = expf(-DT / 0.25f);

#pragma unroll
    for (int i = 0; i < 2; i++) {
        const int b = b0 + ty + 16 * i;
        const float xv = x[b * LL + t];  // N_INP == 1
#pragma unroll
        for (int j = 0; j < 4; j++) {
            const int n = n0 + tx * 4 + j;
            const int idx = b * NH + n;

            float hy = hy_in[idx];
            float hz = g_hz[idx];
            float rf = g_ref[idx];

            float pre = tanhf(acc[i][j] + xv * x2h[n] + bias[n]);
            hz = hz + DT * (pre - gamma[n] * hy - eps[n] * hz);
            hy = hy + DT * hz;

            float s = (hy - THETA - rf > 0.f) ? 1.f : 0.f;
            hy = hy * (1.f - s * ALPHA);
            hz = hz * (1.f - s * BETA);
            rf = rf * ref_decay + s;

            hy_out[idx] = hy;
            g_hz[idx] = hz;
            g_ref[idx] = rf;
            g_ssum[idx] += s;
        }
    }
}

__global__ void finalize_kernel(float* __restrict__ out) {
    int i = blockIdx.x * blockDim.x + threadIdx.x;
    if (i < BB * NH) {
        out[i] = g_ssum[i] * (1.f / (float)LL);
    }
}

extern "C" void kernel_launch(void* const* d_in, const int* in_sizes, int n_in,
                              void* d_out, int out_size) {
    const float* x     = (const float*)d_in[0];
    const float* h2h   = (const float*)d_in[1];
    const float* x2h   = (const float*)d_in[2];
    const float* bias  = (const float*)d_in[3];
    const float* gamma = (const float*)d_in[4];
    const float* eps   = (const float*)d_in[5];
    float* out = (float*)d_out;

    float *hyA, *hyB;
    cudaGetSymbolAddress((void**)&hyA, g_hyA);
    cudaGetSymbolAddress((void**)&hyB, g_hyB);

    init_kernel<<<(BB * NH + 255) / 256, 256>>>();

    dim3 grid(NH / TN, BB / TM);  // 32 x 4 = 128 blocks
    for (int t = 0; t < LL; t++) {
        const float* in = (t & 1) ? hyB : hyA;
        float* outbuf   = (t & 1) ? hyA : hyB;
        step_kernel<<<grid, 256>>>(in, outbuf, x, h2h, x2h, bias, gamma, eps, t);
    }

    finalize_kernel<<<(BB * NH + 255) / 256, 256>>>(out);
    (void)in_sizes; (void)n_in; (void)out_size;
}